// round 2
// baseline (speedup 1.0000x reference)
#include <cuda_runtime.h>
#include <math.h>

#define FNUM   20
#define NPAIR  190          // 20*19/2
#define VTOT   1000000      // sum of field dims
#define ED     16
#define FIELDW 50000
#define SPB    4            // samples per block (2 warps each -> 8 warps = 256 thr)

__global__ __launch_bounds__(256)
void ffm_kernel(const int* __restrict__ x,
                const float* __restrict__ Wl,
                const float* __restrict__ Wc,
                const float* __restrict__ bias,
                float* __restrict__ out, int B)
{
    __shared__ int   sx[SPB][FNUM];
    __shared__ float part[SPB][2];
    __shared__ unsigned char pi[NPAIR], pj[NPAIR];

    int tid  = threadIdx.x;
    int w    = tid >> 5;
    int lane = tid & 31;
    int s    = w >> 1;        // sample slot within block: 0..3
    int half = w & 1;         // which half of the 190 pairs
    int sample = blockIdx.x * SPB + s;

    // parallel pair-LUT build: thread p computes (i,j) for pair p
    if (tid < NPAIR) {
        int i = 0, r = tid;
        while (r >= 19 - i) { r -= 19 - i; i++; }
        pi[tid] = (unsigned char)i;
        pj[tid] = (unsigned char)(i + 1 + r);
    }

    // half-0 warp loads the 20 offset indices for its sample
    if (half == 0 && lane < FNUM && sample < B)
        sx[s][lane] = x[sample * FNUM + lane] + lane * FIELDW;
    __syncthreads();
    if (sample >= B) return;

    float acc = 0.f;
    // linear term handled by the half-0 warp
    if (half == 0 && lane < FNUM)
        acc = Wl[sx[s][lane]];

    const int quad = lane >> 2;        // 0..7  : pair within iteration
    const int kc   = (lane & 3) * 4;   // 0,4,8,12 : embed-dim chunk
    const int pbase = half * 96;       // half0: pairs 0..95, half1: 96..189

    #pragma unroll 4
    for (int it = 0; it < 12; it++) {
        int p = pbase + it * 8 + quad;
        if (p < NPAIR) {
            int i = pi[p];
            int j = pj[p];
            long xi = sx[s][i];
            long xj = sx[s][j];
            const float4 a = *(const float4*)(Wc + ((long)j * VTOT + xi) * ED + kc);
            const float4 b = *(const float4*)(Wc + ((long)i * VTOT + xj) * ED + kc);
            acc += a.x * b.x + a.y * b.y + a.z * b.z + a.w * b.w;
        }
    }

    // warp tree-reduce
    #pragma unroll
    for (int sh = 16; sh; sh >>= 1)
        acc += __shfl_xor_sync(0xffffffffu, acc, sh);

    if (lane == 0) part[s][half] = acc;
    __syncthreads();

    if (half == 0 && lane == 0) {
        float z = part[s][0] + part[s][1] + bias[0];
        out[sample] = 1.f / (1.f + __expf(-z));
    }
}

extern "C" void kernel_launch(void* const* d_in, const int* in_sizes, int n_in,
                              void* d_out, int out_size)
{
    const int*   x  = (const int*)  d_in[0];
    const float* Wl = (const float*)d_in[1];
    const float* Wc = (const float*)d_in[2];
    const float* bs = (const float*)d_in[3];
    float* out = (float*)d_out;

    int B = in_sizes[0] / FNUM;
    int blocks = (B + SPB - 1) / SPB;
    ffm_kernel<<<blocks, 256>>>(x, Wl, Wc, bs, out, B);
}

// round 9
// speedup vs baseline: 1.5493x; 1.5493x over previous
#include <cuda_runtime.h>
#include <math.h>
#include <stdint.h>

#define FNUM   20
#define NPAIR  190          // 20*19/2
#define VTOT   1000000      // sum of field dims
#define ED     16
#define FIELDW 50000
#define WPB    8            // warps per block, 1 sample per warp
#define PIN_T  10           // tables [0, PIN_T) are L2-pinned via evict_last policy

// 16B gather with an L2 cache-hint policy attached
__device__ __forceinline__ float4 ld_hint(const float* p, uint64_t pol) {
    float4 v;
    asm volatile("ld.global.nc.L2::cache_hint.v4.f32 {%0,%1,%2,%3}, [%4], %5;"
                 : "=f"(v.x), "=f"(v.y), "=f"(v.z), "=f"(v.w)
                 : "l"(p), "l"(pol));
    return v;
}

__global__ __launch_bounds__(256, 4)
void ffm_kernel(const int* __restrict__ x,
                const float* __restrict__ Wl,
                const float* __restrict__ Wc,
                const float* __restrict__ bias,
                float* __restrict__ out, int B)
{
    __shared__ int sx[WPB][FNUM];
    __shared__ unsigned char pi[NPAIR], pj[NPAIR];
    __shared__ uint64_t pol_tab[FNUM];

    int tid = threadIdx.x;
    // parallel pair-LUT build: thread p computes (i,j) for pair p
    if (tid < NPAIR) {
        int i = 0, r = tid;
        while (r >= 19 - i) { r -= 19 - i; i++; }
        pi[tid] = (unsigned char)i;
        pj[tid] = (unsigned char)(i + 1 + r);
    }
    // per-table eviction policy: evict_last for pinned tables, evict_first for streaming
    if (tid < FNUM) {
        uint64_t pol;
        if (tid < PIN_T)
            asm volatile("createpolicy.fractional.L2::evict_last.b64 %0, 1.0;"  : "=l"(pol));
        else
            asm volatile("createpolicy.fractional.L2::evict_first.b64 %0, 1.0;" : "=l"(pol));
        pol_tab[tid] = pol;
    }

    int w      = tid >> 5;
    int lane   = tid & 31;
    int sample = blockIdx.x * WPB + w;

    if (lane < FNUM && sample < B)
        sx[w][lane] = x[sample * FNUM + lane] + lane * FIELDW;
    __syncthreads();
    if (sample >= B) return;

    float acc = 0.f;
    // linear term: lanes 0..19 each fetch one W_linear entry
    if (lane < FNUM)
        acc = Wl[sx[w][lane]];

    const int quad = lane >> 2;        // 0..7  : pair within iteration
    const int kc   = (lane & 3) * 4;   // 0,4,8,12 : embed-dim chunk

    #pragma unroll 4
    for (int it = 0; it < 24; it++) {
        int p = it * 8 + quad;
        if (p < NPAIR) {
            int i  = pi[p];
            int j  = pj[p];
            long xi = sx[w][i];
            long xj = sx[w][j];
            const float* pa = Wc + ((long)j * VTOT + xi) * ED + kc;  // table j
            const float* pb = Wc + ((long)i * VTOT + xj) * ED + kc;  // table i
            float4 a = ld_hint(pa, pol_tab[j]);
            float4 b = ld_hint(pb, pol_tab[i]);
            acc += a.x * b.x + a.y * b.y + a.z * b.z + a.w * b.w;
        }
    }

    // warp tree-reduce
    #pragma unroll
    for (int s = 16; s; s >>= 1)
        acc += __shfl_xor_sync(0xffffffffu, acc, s);

    if (lane == 0) {
        float z = acc + bias[0];
        out[sample] = 1.f / (1.f + __expf(-z));
    }
}

extern "C" void kernel_launch(void* const* d_in, const int* in_sizes, int n_in,
                              void* d_out, int out_size)
{
    const int*   x  = (const int*)  d_in[0];
    const float* Wl = (const float*)d_in[1];
    const float* Wc = (const float*)d_in[2];
    const float* bs = (const float*)d_in[3];
    float* out = (float*)d_out;

    int B = in_sizes[0] / FNUM;
    int blocks = (B + WPB - 1) / WPB;
    ffm_kernel<<<blocks, 256>>>(x, Wl, Wc, bs, out, B);
}